// round 14
// baseline (speedup 1.0000x reference)
#include <cuda_runtime.h>

// x is [B, T] float32.
#define BB 64
#define TT 262144
#define BPR 16                     // blocks per row
#define BLK (TT / BPR)             // 16384 samples per block
#define NBLK (BB * BPR)            // 1024 blocks — single co-resident wave (<=1184)
#define WPB 4                      // warps per block (128 threads)
#define WSPAN (BLK / WPB)          // 4096 samples per warp
#define TILES (WSPAN / 256)        // 16 tiles of 256 samples (8/lane)

// Decoupled-lookback state (u-space complex, fp32 value + int flag).
__device__ float2 g_agg[NBLK];
__device__ float2 g_incl[NBLK];
__device__ int    g_flag[NBLK];    // 0 = none, 1 = aggregate, 2 = inclusive

struct SC {
    float2 lvl[5];     // c^(8*2^r)
    float2 ilvl[5];    // c^(-8*2^r)
    float2 i8;         // c^-8
    float2 c8;         // c^8
    float2 c256;       // per-tile advance
    float2 ic256;      // c^-256
    float2 K0;         // c^(8*511) — phase-A accumulate start constant
    float2 wcoef[8];   // (w1_k, w2_k): y-homog coefficients from c^(k+1)
    float  alpha, beta, invbeta;
    float  na1, na2, b0, b1, b2;
    double c4096r, c4096i;     // per-warp-span advance (double)
    double cBr, cBi;           // per-block advance c^16384 (double)
};

__device__ __forceinline__ void build_sc(const float* ac, const float* bc, SC* sc) {
    double a0 = (double)ac[0];
    double a1 = (double)ac[1] / a0, a2 = (double)ac[2] / a0;
    double al = -0.5 * a1;
    double be = sqrt(a2 - al * al);
    sc->alpha = (float)al; sc->beta = (float)be; sc->invbeta = (float)(1.0 / be);
    sc->na1 = (float)(-a1); sc->na2 = (float)(-a2);
    sc->b0 = (float)((double)bc[0] / a0);
    sc->b1 = (float)((double)bc[1] / a0);
    sc->b2 = (float)((double)bc[2] / a0);

    // wcoef[k] from c^(k+1):  h_k = w1*E.x + w2*E.y,
    // w1 = alpha*Re - beta*Im, w2 = -(alpha*Im + beta*Re).
    {
        double pr = 1.0, pi = 0.0;
        for (int k = 0; k < 8; ++k) {
            double nr = pr * al - pi * be;
            double ni = pr * be + pi * al;
            pr = nr; pi = ni;                    // c^(k+1)
            sc->wcoef[k] = make_float2((float)(al * pr - be * pi),
                                       (float)(-(al * pi + be * pr)));
        }
    }

    double cr = al, ci = be;   // c
    for (int i = 0; i < 3; ++i) { double nr = cr*cr - ci*ci, ni = 2.0*cr*ci; cr = nr; ci = ni; } // c^8
    double c8r = cr, c8i = ci;
    sc->c8 = make_float2((float)c8r, (float)c8i);
    for (int r = 0; r < 5; ++r) {
        sc->lvl[r] = make_float2((float)cr, (float)ci);
        double n = cr*cr + ci*ci;
        sc->ilvl[r] = make_float2((float)(cr / n), (float)(-ci / n));
        if (r == 0) sc->i8 = sc->ilvl[0];
        double nr = cr*cr - ci*ci, ni = 2.0*cr*ci; cr = nr; ci = ni;
    }
    // cr,ci = c^256
    sc->c256 = make_float2((float)cr, (float)ci);
    {
        double n = cr*cr + ci*ci;
        sc->ic256 = make_float2((float)(cr / n), (float)(-ci / n));
    }
    for (int i = 0; i < 4; ++i) { double nr = cr*cr - ci*ci, ni = 2.0*cr*ci; cr = nr; ci = ni; } // c^4096
    sc->c4096r = cr; sc->c4096i = ci;
    // K0 = c^4096 * c^-8 = c^(8*511)
    {
        double n8 = c8r*c8r + c8i*c8i;
        double i8r = c8r / n8, i8i = -c8i / n8;
        sc->K0 = make_float2((float)(cr * i8r - ci * i8i), (float)(cr * i8i + ci * i8r));
    }
    { double nr = cr*cr - ci*ci, ni = 2.0*cr*ci; cr = nr; ci = ni; } // c^8192
    { double nr = cr*cr - ci*ci, ni = 2.0*cr*ci; cr = nr; ci = ni; } // c^16384
    sc->cBr = cr; sc->cBi = ci;
}

__device__ __forceinline__ float2 cmulf(float2 a, float2 b) {
    return make_float2(fmaf(a.x, b.x, -a.y * b.y), fmaf(a.x, b.y, a.y * b.x));
}

#define FIR8(f, va, vb, xm1, xm2, b0, b1, b2)                         \
    f[0] = fmaf(b1, xm1,  fmaf(b2, xm2,  b0 * va.x));                 \
    f[1] = fmaf(b1, va.x, fmaf(b2, xm1,  b0 * va.y));                 \
    f[2] = fmaf(b1, va.y, fmaf(b2, va.x, b0 * va.z));                 \
    f[3] = fmaf(b1, va.z, fmaf(b2, va.y, b0 * va.w));                 \
    f[4] = fmaf(b1, va.w, fmaf(b2, va.z, b0 * vb.x));                 \
    f[5] = fmaf(b1, vb.x, fmaf(b2, va.w, b0 * vb.y));                 \
    f[6] = fmaf(b1, vb.y, fmaf(b2, vb.x, b0 * vb.z));                 \
    f[7] = fmaf(b1, vb.z, fmaf(b2, vb.y, b0 * vb.w));

#define IIR8(y, f, na1, na2)                                          \
    y[0] = f[0];                                                      \
    y[1] = fmaf(na1, y[0], f[1]);                                     \
    y[2] = fmaf(na1, y[1], fmaf(na2, y[0], f[2]));                    \
    y[3] = fmaf(na1, y[2], fmaf(na2, y[1], f[3]));                    \
    y[4] = fmaf(na1, y[3], fmaf(na2, y[2], f[4]));                    \
    y[5] = fmaf(na1, y[4], fmaf(na2, y[3], f[5]));                    \
    y[6] = fmaf(na1, y[5], fmaf(na2, y[4], f[6]));                    \
    y[7] = fmaf(na1, y[6], fmaf(na2, y[5], f[7]));

__global__ __launch_bounds__(128, 8) void k_main(
    const float* __restrict__ x,
    const float* __restrict__ ac,
    const float* __restrict__ bc,
    const float* __restrict__ gainp,
    float* __restrict__ out)
{
    __shared__ SC sc;
    __shared__ float2  sWarpAgg[WPB];   // per-warp zero-IC u totals
    __shared__ float2  sEntry[WPB];     // corrected u entry per warp
    __shared__ double2 sE[WPB];         // zero-IC u state entering warp w

    int tid = threadIdx.x;
    int w = tid >> 5, lane = tid & 31;
    int bid = blockIdx.x;
    int row = bid >> 4, blkInRow = bid & 15;
    size_t base = (size_t)row * TT + (size_t)blkInRow * BLK;

    if (tid == 0) build_sc(ac, bc, &sc);
    __syncthreads();

    float na1 = sc.na1, na2 = sc.na2, b0 = sc.b0, b1 = sc.b1, b2 = sc.b2;
    float alpha = sc.alpha, invbeta = sc.invbeta;
    float2 c256 = sc.c256;

    // Per-lane basis constants.
    float2 sd = sc.i8, su = make_float2(1.f, 0.f);
    if (lane & 1)  { sd = cmulf(sd, sc.ilvl[0]); su = cmulf(su, sc.lvl[0]); }
    if (lane & 2)  { sd = cmulf(sd, sc.ilvl[1]); su = cmulf(su, sc.lvl[1]); }
    if (lane & 4)  { sd = cmulf(sd, sc.ilvl[2]); su = cmulf(su, sc.lvl[2]); }
    if (lane & 8)  { sd = cmulf(sd, sc.ilvl[3]); su = cmulf(su, sc.lvl[3]); }
    if (lane & 16) { sd = cmulf(sd, sc.ilvl[4]); su = cmulf(su, sc.lvl[4]); }
    float2 sdA = cmulf(sd, sc.c8);   // c^(-8*lane) for phase A

    size_t wstart = base + (size_t)w * WSPAN;
    const float4* xv = reinterpret_cast<const float4*>(x + wstart);

    // Boundary x for this warp's span (global n<0 -> zeros).
    float bx1 = 0.f, bx2 = 0.f;
    if (blkInRow || w) { bx1 = x[wstart - 1]; bx2 = x[wstart - 2]; }

    // ---------------- Phase A: shuffle-free accumulate, one final reduce ----
    {
        float pv_w = bx1, pv_z = bx2;
        float2 acc = make_float2(0.f, 0.f);
        float2 Kc = sc.K0;
        float2 ic256 = sc.ic256;
        float4 va = xv[2 * lane], vb = xv[2 * lane + 1];
#pragma unroll 4
        for (int t = 0; t < TILES; ++t) {
            float4 nva, nvb;
            if (t + 1 < TILES) {
                nva = xv[(t + 1) * 64 + 2 * lane];
                nvb = xv[(t + 1) * 64 + 2 * lane + 1];
            }
            float xm1 = __shfl_up_sync(0xffffffffu, vb.w, 1);
            float xm2 = __shfl_up_sync(0xffffffffu, vb.z, 1);
            if (lane == 0) { xm1 = pv_w; xm2 = pv_z; }

            float f[8], y[8];
            FIR8(f, va, vb, xm1, xm2, b0, b1, b2);
            IIR8(y, f, na1, na2);

            float2 u = make_float2(y[6], fmaf(alpha, y[6], -y[7]) * invbeta);
            float2 g = cmulf(u, Kc);
            float2 h = cmulf(g, sdA);
            acc.x += h.x; acc.y += h.y;
            Kc = cmulf(Kc, ic256);

            pv_w = __shfl_sync(0xffffffffu, vb.w, 31);
            pv_z = __shfl_sync(0xffffffffu, vb.z, 31);
            va = nva; vb = nvb;
        }
#pragma unroll
        for (int s = 16; s > 0; s >>= 1) {
            acc.x += __shfl_down_sync(0xffffffffu, acc.x, s);
            acc.y += __shfl_down_sync(0xffffffffu, acc.y, s);
        }
        if (lane == 0) sWarpAgg[w] = acc;
    }
    __syncthreads();

    // ---------------- Thread 0: combine, publish, lookback, entries ----------------
    if (tid == 0) {
        double c4r = sc.c4096r, c4i = sc.c4096i;
        double cbr = sc.cBr, cbi = sc.cBi;
        double e1 = 0.0, e2 = 0.0;
#pragma unroll
        for (int ww = 0; ww < WPB; ++ww) {
            sE[ww] = make_double2(e1, e2);
            float2 S = sWarpAgg[ww];
            double t1 = c4r * e1 - c4i * e2 + (double)S.x;
            double t2 = c4i * e1 + c4r * e2 + (double)S.y;
            e1 = t1; e2 = t2;
        }
        g_agg[bid] = make_float2((float)e1, (float)e2);
        __threadfence();

        double P1 = 0.0, P2 = 0.0;
        if (blkInRow == 0) {
            g_incl[bid] = make_float2((float)e1, (float)e2);
            __threadfence();
            *(volatile int*)&g_flag[bid] = 2;
        } else {
            *(volatile int*)&g_flag[bid] = 1;
            double M1 = 1.0, M2 = 0.0;
            int j = bid - 1;
            while (true) {
                int f;
                while ((f = *(volatile int*)&g_flag[j]) == 0) __nanosleep(32);
                __threadfence();
                volatile float* vp = (f == 2) ? (volatile float*)&g_incl[j]
                                              : (volatile float*)&g_agg[j];
                double Vx = (double)vp[0], Vy = (double)vp[1];
                P1 += M1 * Vx - M2 * Vy;
                P2 += M1 * Vy + M2 * Vx;
                if (f == 2) break;
                double m1 = M1 * cbr - M2 * cbi;
                M2 = M1 * cbi + M2 * cbr;
                M1 = m1;
                --j;
            }
            double i1 = cbr * P1 - cbi * P2 + e1;
            double i2 = cbi * P1 + cbr * P2 + e2;
            g_incl[bid] = make_float2((float)i1, (float)i2);
            __threadfence();
            *(volatile int*)&g_flag[bid] = 2;
        }
        double Q1 = P1, Q2 = P2;
#pragma unroll
        for (int ww = 0; ww < WPB; ++ww) {
            double2 E = sE[ww];
            sEntry[ww] = make_float2((float)(Q1 + E.x), (float)(Q2 + E.y));
            double q1 = c4r * Q1 - c4i * Q2;
            Q2 = c4i * Q1 + c4r * Q2;
            Q1 = q1;
        }
    }
    __syncthreads();

    // ---------------- Phase C: corrected recompute + output ----------------
    // z_k = y_zic_k + w1_k*E.x + w2_k*E.y  (homogeneous correction, parallel)
    {
        float gain = gainp[0];
        float2 C = sEntry[w];
        float2 W0 = sc.wcoef[0], W1 = sc.wcoef[1], W2 = sc.wcoef[2], W3 = sc.wcoef[3];
        float2 W4 = sc.wcoef[4], W5 = sc.wcoef[5], W6 = sc.wcoef[6], W7 = sc.wcoef[7];
        float4* ov = reinterpret_cast<float4*>(out + wstart);
        float pv_w = bx1, pv_z = bx2;
        float4 va = xv[2 * lane], vb = xv[2 * lane + 1];
#pragma unroll 4
        for (int t = 0; t < TILES; ++t) {
            float4 nva, nvb;
            if (t + 1 < TILES) {
                nva = xv[(t + 1) * 64 + 2 * lane];
                nvb = xv[(t + 1) * 64 + 2 * lane + 1];
            }
            float xm1 = __shfl_up_sync(0xffffffffu, vb.w, 1);
            float xm2 = __shfl_up_sync(0xffffffffu, vb.z, 1);
            if (lane == 0) { xm1 = pv_w; xm2 = pv_z; }

            float f[8], y[8];
            FIR8(f, va, vb, xm1, xm2, b0, b1, b2);
            IIR8(y, f, na1, na2);

            float2 u = make_float2(y[6], fmaf(alpha, y[6], -y[7]) * invbeta);
            float2 ww2 = cmulf(u, sd);
#pragma unroll
            for (int s = 1; s < 32; s <<= 1) {
                float px = __shfl_up_sync(0xffffffffu, ww2.x, s);
                float py = __shfl_up_sync(0xffffffffu, ww2.y, s);
                if (lane >= s) { ww2.x += px; ww2.y += py; }
            }
            float Sx = __shfl_sync(0xffffffffu, ww2.x, 31);
            float Sy = __shfl_sync(0xffffffffu, ww2.y, 31);
            float ex = __shfl_up_sync(0xffffffffu, ww2.x, 1);
            float ey = __shfl_up_sync(0xffffffffu, ww2.y, 1);
            if (lane == 0) { ex = 0.f; ey = 0.f; }

            // per-lane entry state in u (E), then parallel homog correction
            float2 E = cmulf(make_float2(C.x + ex, C.y + ey), su);

            float z0 = y[0] + fmaf(W0.x, E.x, W0.y * E.y);
            float z1 = y[1] + fmaf(W1.x, E.x, W1.y * E.y);
            float z2 = y[2] + fmaf(W2.x, E.x, W2.y * E.y);
            float z3 = y[3] + fmaf(W3.x, E.x, W3.y * E.y);
            float z4 = y[4] + fmaf(W4.x, E.x, W4.y * E.y);
            float z5 = y[5] + fmaf(W5.x, E.x, W5.y * E.y);
            float z6 = y[6] + fmaf(W6.x, E.x, W6.y * E.y);
            float z7 = y[7] + fmaf(W7.x, E.x, W7.y * E.y);

            float4 oa, ob;
            oa.x = gain * fminf(1.f, fmaxf(-1.f, z0));
            oa.y = gain * fminf(1.f, fmaxf(-1.f, z1));
            oa.z = gain * fminf(1.f, fmaxf(-1.f, z2));
            oa.w = gain * fminf(1.f, fmaxf(-1.f, z3));
            ob.x = gain * fminf(1.f, fmaxf(-1.f, z4));
            ob.y = gain * fminf(1.f, fmaxf(-1.f, z5));
            ob.z = gain * fminf(1.f, fmaxf(-1.f, z6));
            ob.w = gain * fminf(1.f, fmaxf(-1.f, z7));
            __stcs(&ov[t * 64 + 2 * lane],     oa);
            __stcs(&ov[t * 64 + 2 * lane + 1], ob);

            C = cmulf(make_float2(C.x + Sx, C.y + Sy), c256);

            pv_w = __shfl_sync(0xffffffffu, vb.w, 31);
            pv_z = __shfl_sync(0xffffffffu, vb.z, 31);
            va = nva; vb = nvb;
        }
    }
}

extern "C" void kernel_launch(void* const* d_in, const int* in_sizes, int n_in,
                              void* d_out, int out_size)
{
    const float* x    = (const float*)d_in[0];
    const float* ac   = (const float*)d_in[1];
    const float* bc   = (const float*)d_in[2];
    const float* gain = (const float*)d_in[3];
    float* out = (float*)d_out;

    int* flagp;
    cudaGetSymbolAddress((void**)&flagp, g_flag);
    cudaMemsetAsync(flagp, 0, NBLK * sizeof(int));
    k_main<<<NBLK, 128>>>(x, ac, bc, gain, out);
}